// round 17
// baseline (speedup 1.0000x reference)
#include <cuda_runtime.h>
#include <cuda_bf16.h>
#include <math.h>
#include <stdint.h>

// Problem constants
#define BATCH   2
#define S_LEN   2048
#define NHEAD   16
#define HD      64
#define DMODEL  1024   // NHEAD*HD
#define NPAIRS  32     // HD/2
#define NTOK    (BATCH*S_LEN)   // 4096
#define NBH     (BATCH*NHEAD)   // 32

typedef unsigned long long ull;
typedef unsigned short u16;

// Scratch (device globals — no allocation allowed).
// Only referenced from device code (GB300 host-shadow/ATS pitfall).
__device__ int   g_pos[NTOK*3];
__device__ int   g_is64;
__device__ float g_cos[NPAIRS*32];
__device__ float g_sin[NPAIRS*32];

// bf16 hi/lo split operands (raw u16 bits)
__device__ __align__(16) u16 g_Qhi[NBH*S_LEN*HD];
__device__ __align__(16) u16 g_Qlo[NBH*S_LEN*HD];
__device__ __align__(16) u16 g_Khi[NBH*S_LEN*HD];
__device__ __align__(16) u16 g_Klo[NBH*S_LEN*HD];
__device__ __align__(16) u16 g_Vhi[NBH*S_LEN*HD];
__device__ __align__(16) u16 g_Vlo[NBH*S_LEN*HD];

// attention output, pre-split for the out-proj GEMM
__device__ __align__(16) u16 g_aHi[NTOK*DMODEL];
__device__ __align__(16) u16 g_aLo[NTOK*DMODEL];

__device__ __align__(16) __nv_bfloat16 g_wqkvT_hi[3*DMODEL*DMODEL];
__device__ __align__(16) __nv_bfloat16 g_wqkvT_lo[3*DMODEL*DMODEL];
__device__ __align__(16) __nv_bfloat16 g_woutT_hi[DMODEL*DMODEL];
__device__ __align__(16) __nv_bfloat16 g_woutT_lo[DMODEL*DMODEL];

#define NEGINF __int_as_float(0xff800000)

// ---------------------------------------------------------------------------
// helpers
// ---------------------------------------------------------------------------
__device__ __forceinline__ uint32_t cvt_bf16x2(float hi_elem, float lo_elem) {
    uint32_t r;
    asm("cvt.rn.bf16x2.f32 %0, %1, %2;" : "=r"(r) : "f"(hi_elem), "f"(lo_elem));
    return r;
}

__device__ __forceinline__ uint32_t smem_u32(const void* p) {
    uint32_t a;
    asm("{ .reg .u64 t; cvta.to.shared.u64 t, %1; cvt.u32.u64 %0, t; }" : "=r"(a) : "l"(p));
    return a;
}

// mma.sync m16n8k16 bf16 (arch-agnostic PTX, sm_80+)
__device__ __forceinline__ void mma16816(float* c, const uint32_t* a, const uint32_t* b) {
    asm volatile(
        "mma.sync.aligned.m16n8k16.row.col.f32.bf16.bf16.f32 "
        "{%0,%1,%2,%3}, {%4,%5,%6,%7}, {%8,%9}, {%0,%1,%2,%3};"
        : "+f"(c[0]), "+f"(c[1]), "+f"(c[2]), "+f"(c[3])
        : "r"(a[0]), "r"(a[1]), "r"(a[2]), "r"(a[3]), "r"(b[0]), "r"(b[1]));
}

// ldmatrix x4 (sm_75+), addr = 32-bit shared address
#define LDSM_X4(r, addr) \
    asm volatile("ldmatrix.sync.aligned.m8n8.x4.shared.b16 {%0,%1,%2,%3}, [%4];" \
        : "=r"((r)[0]), "=r"((r)[1]), "=r"((r)[2]), "=r"((r)[3]) : "r"(addr))
#define LDSM_X4_T(r, addr) \
    asm volatile("ldmatrix.sync.aligned.m8n8.x4.trans.shared.b16 {%0,%1,%2,%3}, [%4];" \
        : "=r"((r)[0]), "=r"((r)[1]), "=r"((r)[2]), "=r"((r)[3]) : "r"(addr))

// cp.async (sm_80+)
#define CP_ASYNC16(daddr, gptr) \
    asm volatile("cp.async.ca.shared.global [%0], [%1], 16;" \
        :: "r"(daddr), "l"(gptr) : "memory")
#define CP_COMMIT() asm volatile("cp.async.commit_group;" ::: "memory")
#define CP_WAIT0()  asm volatile("cp.async.wait_group 0;" ::: "memory")

// ---------------------------------------------------------------------------
// Position dtype detection + conversion
// ---------------------------------------------------------------------------
__global__ void detect_pos64(const int* __restrict__ raw, int n_words) {
    __shared__ int red[256];
    int acc = 0;
    for (int i = threadIdx.x; 2*i + 1 < n_words; i += 256)
        acc |= raw[2*i + 1];
    red[threadIdx.x] = acc;
    __syncthreads();
    for (int s1 = 128; s1 > 0; s1 >>= 1) {
        if (threadIdx.x < s1) red[threadIdx.x] |= red[threadIdx.x + s1];
        __syncthreads();
    }
    if (threadIdx.x == 0) g_is64 = (red[0] == 0) ? 1 : 0;
}

__global__ void convert_pos(const int* __restrict__ raw, int n) {
    int i = blockIdx.x * 256 + threadIdx.x;
    if (i >= n) return;
    int v = g_is64 ? raw[2*i] : raw[i];
    int ax = i % 3;
    int mx = (ax == 2) ? 7 : 31;
    v = v < 0 ? 0 : (v > mx ? mx : v);
    g_pos[i] = v;
}

__global__ void build_tables() {
    int t = threadIdx.x;            // 1024 threads
    int p = t >> 5, pos = t & 31;
    float inv;
    if (p < 10)      inv = powf(10000.0f, -(2.0f * p)        / 20.0f);
    else if (p < 20) inv = powf(10000.0f, -(2.0f * (p - 10)) / 20.0f);
    else             inv = powf(10000.0f, -(2.0f * (p - 20)) / 24.0f);
    float ang = (float)pos * inv;
    g_cos[t] = cosf(ang);
    g_sin[t] = sinf(ang);
}

// ---------------------------------------------------------------------------
// Transpose W[K][N] -> T[N][K] with bf16 hi/lo split.
// ---------------------------------------------------------------------------
__global__ void transpose_split(const float* __restrict__ W, int K, int N, int which) {
    __shared__ float tile[32][33];
    __nv_bfloat16* Thi = which ? g_woutT_hi : g_wqkvT_hi;
    __nv_bfloat16* Tlo = which ? g_woutT_lo : g_wqkvT_lo;
    int k0 = blockIdx.y * 32, n0 = blockIdx.x * 32;
    int x = threadIdx.x, y = threadIdx.y;
    #pragma unroll
    for (int i = y; i < 32; i += 8)
        tile[i][x] = W[(size_t)(k0 + i)*N + n0 + x];
    __syncthreads();
    #pragma unroll
    for (int i = y; i < 32; i += 8) {
        float f = tile[x][i];
        __nv_bfloat16 h = __float2bfloat16_rn(f);
        float r = f - __bfloat162float(h);
        size_t o = (size_t)(n0 + i)*K + k0 + x;
        Thi[o] = h;
        Tlo[o] = __float2bfloat16_rn(r);
    }
}

// ---------------------------------------------------------------------------
// mma.sync bf16x3 GEMM, double-buffered.
// mode 1: A = fp32 hidden_states (register-split); RoPE-fused scatter epilogue.
// mode 2: A = g_aHi/g_aLo pre-split (cp.async); plain fp32 C write.
// Dynamic smem: 2 stages x (Ahi|Alo|Bhi|Blo) x 128 x ASTR u16 = 81920 B.
// ---------------------------------------------------------------------------
#define GK   1024
#define ASTR 40
#define STG_BYTES (4*128*ASTR*2)      // 40960 B per stage
#define GEMM_SMEM (2*STG_BYTES)       // 81920 B

__global__ __launch_bounds__(256)
void mma_gemm(const float* __restrict__ Aext, float* __restrict__ C,
              int N_total, int mode)
{
    extern __shared__ u16 dsm[];

    const __nv_bfloat16 *Bhi, *Blo;
    if (mode == 1) { Bhi = g_wqkvT_hi; Blo = g_wqkvT_lo; }
    else           { Bhi = g_woutT_hi; Blo = g_woutT_lo; }

    const int tid  = threadIdx.x;
    const int lane = tid & 31;
    const int wid  = tid >> 5;
    const int warp_m = wid >> 2;        // 0..1
    const int warp_n = wid & 3;         // 0..3
    const int g = lane >> 2, t = lane & 3;
    const int m0 = blockIdx.y * 128;
    const int n0 = blockIdx.x * 128;

    const uint32_t dbase = smem_u32(dsm);

    // ldmatrix lane addressing
    const int lrow = lane & 7;
    const int lsel = lane >> 3;
    const int a_roff = (lsel & 1)*8 + lrow;
    const int a_koff = (lsel >> 1)*8;
    const int b_roff = (lsel >> 1)*8 + lrow;
    const int b_koff = (lsel & 1)*8;

    float4 apref[4];

    auto loadA1 = [&](int ch) {       // mode 1: fp32 -> regs
        #pragma unroll
        for (int it = 0; it < 4; ++it) {
            int f = tid + it*256;
            int row = f >> 3, seg = f & 7;
            apref[it] = *(const float4*)(Aext + (size_t)(m0 + row)*GK + ch*32 + seg*4);
        }
    };
    auto storeA1 = [&](int st) {      // mode 1: split + store
        u16* sA = dsm + (size_t)st*(STG_BYTES/2);
        #pragma unroll
        for (int it = 0; it < 4; ++it) {
            int f = tid + it*256;
            int row = f >> 3, seg = f & 7;
            float4 v = apref[it];
            uint32_t h0 = cvt_bf16x2(v.y, v.x);
            uint32_t h1 = cvt_bf16x2(v.w, v.z);
            float e0 = __uint_as_float(h0 << 16), e1 = __uint_as_float(h0 & 0xffff0000u);
            float e2 = __uint_as_float(h1 << 16), e3 = __uint_as_float(h1 & 0xffff0000u);
            uint32_t l0 = cvt_bf16x2(v.y - e1, v.x - e0);
            uint32_t l1 = cvt_bf16x2(v.w - e3, v.z - e2);
            *(uint2*)(sA + row*ASTR + seg*4) = make_uint2(h0, h1);
            *(uint2*)(sA + 5120 + row*ASTR + seg*4) = make_uint2(l0, l1);
        }
    };
    auto loadA2 = [&](int st, int ch) {   // mode 2: pre-split via cp.async
        uint32_t bA = dbase + st*STG_BYTES;
        #pragma unroll
        for (int it = 0; it < 4; ++it) {
            int f = tid + it*256;
            int arr = f >> 9;
            int idx = f & 511;
            int row = idx >> 2, seg = idx & 3;
            const u16* src = (arr ? g_aLo : g_aHi)
                + (size_t)(m0 + row)*GK + ch*32 + seg*8;
            CP_ASYNC16(bA + arr*10240 + (row*ASTR + seg*8)*2, src);
        }
    };
    auto loadB = [&](int st, int ch) {
        uint32_t bB = dbase + st*STG_BYTES + 20480;
        #pragma unroll
        for (int it = 0; it < 4; ++it) {
            int f = tid + it*256;
            int arr = f >> 9;
            int idx = f & 511;
            int row = idx >> 2, seg = idx & 3;
            const __nv_bfloat16* src = (arr ? Blo : Bhi)
                + (size_t)(n0 + row)*GK + ch*32 + seg*8;
            CP_ASYNC16(bB + arr*10240 + (row*ASTR + seg*8)*2, src);
        }
    };

    float acc[4][4][4];
    #pragma unroll
    for (int mt = 0; mt < 4; ++mt)
        #pragma unroll
        for (int nt = 0; nt < 4; ++nt)
            #pragma unroll
            for (int q = 0; q < 4; ++q) acc[mt][nt][q] = 0.0f;

    auto compute = [&](int cur) {
        const uint32_t sbase = dbase + cur*STG_BYTES;
        const uint32_t bAhi = sbase;
        const uint32_t bAlo = sbase + 10240;
        const uint32_t bBhi = sbase + 20480;
        const uint32_t bBlo = sbase + 30720;
        #pragma unroll
        for (int kk = 0; kk < 2; ++kk) {
            uint32_t ah[4][4], al[4][4], bfr[2][2][4];
            #pragma unroll
            for (int mt = 0; mt < 4; ++mt) {
                uint32_t off = ((warp_m*64 + mt*16 + a_roff)*ASTR + kk*16 + a_koff)*2;
                LDSM_X4(ah[mt], bAhi + off);
                LDSM_X4(al[mt], bAlo + off);
            }
            #pragma unroll
            for (int ntp = 0; ntp < 2; ++ntp) {
                uint32_t off = ((warp_n*32 + ntp*16 + b_roff)*ASTR + kk*16 + b_koff)*2;
                LDSM_X4(bfr[0][ntp], bBhi + off);
                LDSM_X4(bfr[1][ntp], bBlo + off);
            }
            #pragma unroll
            for (int mt = 0; mt < 4; ++mt)
                #pragma unroll
                for (int nt = 0; nt < 4; ++nt) {
                    const uint32_t* bh2 = &bfr[0][nt >> 1][(nt & 1)*2];
                    const uint32_t* bl2 = &bfr[1][nt >> 1][(nt & 1)*2];
                    mma16816(acc[mt][nt], ah[mt], bh2);
                    mma16816(acc[mt][nt], ah[mt], bl2);
                    mma16816(acc[mt][nt], al[mt], bh2);
                }
        }
    };

    if (mode == 1) {
        loadA1(0);
        loadB(0, 0);
        CP_COMMIT();
        storeA1(0);
        CP_WAIT0();
        __syncthreads();
        for (int ch = 0; ch < GK/32; ++ch) {
            const int cur = ch & 1, nxt = 1 - cur;
            if (ch + 1 < GK/32) {
                loadA1(ch + 1);
                loadB(nxt, ch + 1);
                CP_COMMIT();
            }
            compute(cur);
            if (ch + 1 < GK/32) {
                storeA1(nxt);
                CP_WAIT0();
            }
            __syncthreads();
        }
    } else {
        loadA2(0, 0);
        loadB(0, 0);
        CP_COMMIT();
        CP_WAIT0();
        __syncthreads();
        for (int ch = 0; ch < GK/32; ++ch) {
            const int cur = ch & 1, nxt = 1 - cur;
            if (ch + 1 < GK/32) {
                loadA2(nxt, ch + 1);
                loadB(nxt, ch + 1);
                CP_COMMIT();
            }
            compute(cur);
            CP_WAIT0();
            __syncthreads();
        }
    }

    if (mode == 1) {
        // RoPE-fused scatter. Thread owns cols n, n+1 with d even => RoPE pair.
        #pragma unroll
        for (int mt = 0; mt < 4; ++mt) {
            #pragma unroll
            for (int half = 0; half < 2; ++half) {
                int m = m0 + warp_m*64 + mt*16 + g + half*8;
                int bb = m >> 11, s = m & 2047;
                #pragma unroll
                for (int nt = 0; nt < 4; ++nt) {
                    int n = n0 + warp_n*32 + nt*8 + 2*t;
                    int sec = n >> 10;
                    int r = n & 1023;
                    int h = r >> 6, d = r & 63;
                    size_t idx = ((size_t)((bb*NHEAD + h)*S_LEN + s))*HD + d;
                    float x0 = acc[mt][nt][half*2 + 0];
                    float x1 = acc[mt][nt][half*2 + 1];
                    if (sec < 2) {
                        int p = d >> 1;
                        int ax = (p < 10) ? 0 : ((p < 20) ? 1 : 2);
                        int pos = g_pos[m*3 + ax];
                        float c  = g_cos[p*32 + pos];
                        float sn = g_sin[p*32 + pos];
                        float r0 = x0*c - x1*sn;
                        float r1 = x1*c + x0*sn;
                        uint32_t hv = cvt_bf16x2(r1, r0);
                        float eh0 = __uint_as_float(hv << 16);
                        float eh1 = __uint_as_float(hv & 0xffff0000u);
                        uint32_t lv = cvt_bf16x2(r1 - eh1, r0 - eh0);
                        if (sec == 0) {
                            *(uint32_t*)(g_Qhi + idx) = hv;
                            *(uint32_t*)(g_Qlo + idx) = lv;
                        } else {
                            *(uint32_t*)(g_Khi + idx) = hv;
                            *(uint32_t*)(g_Klo + idx) = lv;
                        }
                    } else {
                        uint32_t hv = cvt_bf16x2(x1, x0);
                        float eh0 = __uint_as_float(hv << 16);
                        float eh1 = __uint_as_float(hv & 0xffff0000u);
                        uint32_t lv = cvt_bf16x2(x1 - eh1, x0 - eh0);
                        *(uint32_t*)(g_Vhi + idx) = hv;
                        *(uint32_t*)(g_Vlo + idx) = lv;
                    }
                }
            }
        }
    } else {
        #pragma unroll
        for (int mt = 0; mt < 4; ++mt) {
            #pragma unroll
            for (int half = 0; half < 2; ++half) {
                int m = m0 + warp_m*64 + mt*16 + g + half*8;
                float* rowp = C + (size_t)m*N_total + n0 + warp_n*32 + 2*t;
                #pragma unroll
                for (int nt = 0; nt < 4; ++nt)
                    *(float2*)(rowp + nt*8) =
                        make_float2(acc[mt][nt][half*2 + 0], acc[mt][nt][half*2 + 1]);
            }
        }
    }
}

// ---------------------------------------------------------------------------
// Flash attention (causal) on mma.sync tensor cores, bf16x3.
// Double-buffered K/V via cp.async. V natural [key][d], PV via ldmatrix.trans.
// Smem: Q(hi,lo) 128x72 + 2 stages x (Kh,Kl,Vh,Vl) 64x72  (u16).
// ---------------------------------------------------------------------------
#define AS2 72
#define KV_STG (4*64*AS2)               // u16 per stage = 18432 (36864 B)
#define ATT_SMEM ((128*AS2*2 + 2*KV_STG) * 2)   // 110592 B

__global__ __launch_bounds__(256, 2)
void attention_mma() {
    extern __shared__ u16 sb[];
    u16* sQh = sb;                       // [128][72]
    u16* sQl = sQh + 128*AS2;
    u16* sKV = sQl + 128*AS2;            // 2 stages

    const int tid  = threadIdx.x;
    const int lane = tid & 31;
    const int wid  = tid >> 5;
    const int g = lane >> 2, t = lane & 3;
    const int lrow = lane & 7, lsel = lane >> 3;
    const int bh = blockIdx.y;
    const int qt = (int)gridDim.x - 1 - (int)blockIdx.x;

    const size_t hb = (size_t)bh * S_LEN;
    const uint32_t bQh = smem_u32(sQh);
    const uint32_t bQl = bQh + 128*AS2*2;
    const uint32_t bKV = bQl + 128*AS2*2;

    // KV stage loader: 4 arrays x 64 rows x 64 u16, 8 cp.async per thread
    auto loadKV = [&](int st, int kt) {
        const u16* srcs[4] = {
            g_Khi + (hb + kt*64)*HD, g_Klo + (hb + kt*64)*HD,
            g_Vhi + (hb + kt*64)*HD, g_Vlo + (hb + kt*64)*HD };
        uint32_t base = bKV + st*(KV_STG*2);
        #pragma unroll
        for (int it = 0; it < 8; ++it) {
            int f = tid + it*256;
            int arr = f >> 9;            // 0..3
            int idx = f & 511;
            int row = idx >> 3, seg = idx & 7;
            CP_ASYNC16(base + arr*(64*AS2*2) + (row*AS2 + seg*8)*2,
                       srcs[arr] + row*HD + seg*8);
        }
    };

    // prologue: Q + stage0 via cp.async
    {
        const u16* Qh = g_Qhi + (hb + qt*128)*HD;
        const u16* Ql = g_Qlo + (hb + qt*128)*HD;
        #pragma unroll
        for (int it = 0; it < 4; ++it) {
            int f = tid + it*256;
            int row = f >> 3, seg = f & 7;
            CP_ASYNC16(bQh + (row*AS2 + seg*8)*2, Qh + row*HD + seg*8);
            CP_ASYNC16(bQl + (row*AS2 + seg*8)*2, Ql + row*HD + seg*8);
        }
        loadKV(0, 0);
        CP_COMMIT();
        CP_WAIT0();
        __syncthreads();
    }

    float o[8][4];
    #pragma unroll
    for (int nt = 0; nt < 8; ++nt)
        #pragma unroll
        for (int q = 0; q < 4; ++q) o[nt][q] = 0.0f;
    float m0 = NEGINF, m1 = NEGINF, l0 = 0.0f, l1 = 0.0f;

    const int rowg = qt*128 + wid*16 + g;
    const int ktmax = 2*qt + 1;

    for (int kt = 0; kt <= ktmax; ++kt) {
        const int cur = kt & 1;
        if (kt + 1 <= ktmax) {
            loadKV(1 - cur, kt + 1);
            CP_COMMIT();
        }
        const uint32_t bKh = bKV + cur*(KV_STG*2);
        const uint32_t bKl = bKh + 64*AS2*2;
        const uint32_t bVh = bKl + 64*AS2*2;
        const uint32_t bVl = bVh + 64*AS2*2;
        const u16* sKh = (const u16*)(sKV + cur*KV_STG);
        const u16* sKl = sKh + 64*AS2;

        float c[8][4];
        #pragma unroll
        for (int nt = 0; nt < 8; ++nt)
            #pragma unroll
            for (int q = 0; q < 4; ++q) c[nt][q] = 0.0f;

        #pragma unroll
        for (int kc = 0; kc < 4; ++kc) {
            const int ar = wid*16 + g;
            const int ko = kc*16 + 2*t;
            uint32_t ah[4], al[4];
            ah[0] = *(const uint32_t*)(sQh + ar*AS2 + ko);
            ah[1] = *(const uint32_t*)(sQh + (ar+8)*AS2 + ko);
            ah[2] = *(const uint32_t*)(sQh + ar*AS2 + ko + 8);
            ah[3] = *(const uint32_t*)(sQh + (ar+8)*AS2 + ko + 8);
            al[0] = *(const uint32_t*)(sQl + ar*AS2 + ko);
            al[1] = *(const uint32_t*)(sQl + (ar+8)*AS2 + ko);
            al[2] = *(const uint32_t*)(sQl + ar*AS2 + ko + 8);
            al[3] = *(const uint32_t*)(sQl + (ar+8)*AS2 + ko + 8);
            #pragma unroll
            for (int nt = 0; nt < 8; ++nt) {
                const int br = nt*8 + g;
                uint32_t bh2[2], bl2[2];
                bh2[0] = *(const uint32_t*)(sKh + br*AS2 + ko);
                bh2[1] = *(const uint32_t*)(sKh + br*AS2 + ko + 8);
                bl2[0] = *(const uint32_t*)(sKl + br*AS2 + ko);
                bl2[1] = *(const uint32_t*)(sKl + br*AS2 + ko + 8);
                mma16816(c[nt], ah, bh2);
                mma16816(c[nt], ah, bl2);
                mma16816(c[nt], al, bh2);
            }
        }

        if (kt >= 2*qt) {
            #pragma unroll
            for (int nt = 0; nt < 8; ++nt) {
                int col = kt*64 + nt*8 + 2*t;
                c[nt][0] = (col     > rowg    ) ? NEGINF : c[nt][0]*0.125f;
                c[nt][1] = (col + 1 > rowg    ) ? NEGINF : c[nt][1]*0.125f;
                c[nt][2] = (col     > rowg + 8) ? NEGINF : c[nt][2]*0.125f;
                c[nt][3] = (col + 1 > rowg + 8) ? NEGINF : c[nt][3]*0.125f;
            }
        } else {
            #pragma unroll
            for (int nt = 0; nt < 8; ++nt) {
                c[nt][0] *= 0.125f; c[nt][1] *= 0.125f;
                c[nt][2] *= 0.125f; c[nt][3] *= 0.125f;
            }
        }

        float rmax0 = NEGINF, rmax1 = NEGINF;
        #pragma unroll
        for (int nt = 0; nt < 8; ++nt) {
            rmax0 = fmaxf(rmax0, fmaxf(c[nt][0], c[nt][1]));
            rmax1 = fmaxf(rmax1, fmaxf(c[nt][2], c[nt][3]));
        }
        rmax0 = fmaxf(rmax0, __shfl_xor_sync(0xffffffffu, rmax0, 1));
        rmax0 = fmaxf(rmax0, __shfl_xor_sync(0xffffffffu, rmax0, 2));
        rmax1 = fmaxf(rmax1, __shfl_xor_sync(0xffffffffu, rmax1, 1));
        rmax1 = fmaxf(rmax1, __shfl_xor_sync(0xffffffffu, rmax1, 2));
        float mn0 = fmaxf(m0, rmax0), mn1 = fmaxf(m1, rmax1);
        float corr0 = __expf(m0 - mn0), corr1 = __expf(m1 - mn1);
        float rs0 = 0.0f, rs1 = 0.0f;
        #pragma unroll
        for (int nt = 0; nt < 8; ++nt) {
            c[nt][0] = __expf(c[nt][0] - mn0);
            c[nt][1] = __expf(c[nt][1] - mn0);
            c[nt][2] = __expf(c[nt][2] - mn1);
            c[nt][3] = __expf(c[nt][3] - mn1);
            rs0 += c[nt][0] + c[nt][1];
            rs1 += c[nt][2] + c[nt][3];
        }
        rs0 += __shfl_xor_sync(0xffffffffu, rs0, 1);
        rs0 += __shfl_xor_sync(0xffffffffu, rs0, 2);
        rs1 += __shfl_xor_sync(0xffffffffu, rs1, 1);
        rs1 += __shfl_xor_sync(0xffffffffu, rs1, 2);
        l0 = l0*corr0 + rs0;  m0 = mn0;
        l1 = l1*corr1 + rs1;  m1 = mn1;
        #pragma unroll
        for (int nt = 0; nt < 8; ++nt) {
            o[nt][0] *= corr0; o[nt][1] *= corr0;
            o[nt][2] *= corr1; o[nt][3] *= corr1;
        }

        // O += P V : P repacked in-register (hi/lo), V via ldmatrix.trans
        #pragma unroll
        for (int kc = 0; kc < 4; ++kc) {
            const int j0 = 2*kc, j1 = 2*kc + 1;
            uint32_t ah[4], al[4];
            {
                uint32_t h0 = cvt_bf16x2(c[j0][1], c[j0][0]);
                uint32_t h1 = cvt_bf16x2(c[j0][3], c[j0][2]);
                uint32_t h2 = cvt_bf16x2(c[j1][1], c[j1][0]);
                uint32_t h3 = cvt_bf16x2(c[j1][3], c[j1][2]);
                ah[0] = h0; ah[1] = h1; ah[2] = h2; ah[3] = h3;
                al[0] = cvt_bf16x2(c[j0][1] - __uint_as_float(h0 & 0xffff0000u),
                                   c[j0][0] - __uint_as_float(h0 << 16));
                al[1] = cvt_bf16x2(c[j0][3] - __uint_as_float(h1 & 0xffff0000u),
                                   c[j0][2] - __uint_as_float(h1 << 16));
                al[2] = cvt_bf16x2(c[j1][1] - __uint_as_float(h2 & 0xffff0000u),
                                   c[j1][0] - __uint_as_float(h2 << 16));
                al[3] = cvt_bf16x2(c[j1][3] - __uint_as_float(h3 & 0xffff0000u),
                                   c[j1][2] - __uint_as_float(h3 << 16));
            }
            const uint32_t roff = (kc*16 + (lsel & 1)*8 + lrow)*AS2 + (lsel >> 1)*8;
            #pragma unroll
            for (int ntp = 0; ntp < 4; ++ntp) {
                uint32_t off = (roff + ntp*16)*2;
                uint32_t bh4[4], bl4[4];
                LDSM_X4_T(bh4, bVh + off);
                LDSM_X4_T(bl4, bVl + off);
                mma16816(o[2*ntp + 0], ah, bh4 + 0);
                mma16816(o[2*ntp + 0], ah, bl4 + 0);
                mma16816(o[2*ntp + 0], al, bh4 + 0);
                mma16816(o[2*ntp + 1], ah, bh4 + 2);
                mma16816(o[2*ntp + 1], ah, bl4 + 2);
                mma16816(o[2*ntp + 1], al, bh4 + 2);
            }
        }

        CP_WAIT0();
        __syncthreads();
    }

    // epilogue: write bf16 hi/lo splits directly (feeds out-proj GEMM)
    const int b = bh >> 4, h = bh & 15;
    const float inv0 = 1.0f / l0, inv1 = 1.0f / l1;
    const int sg0 = qt*128 + wid*16 + g;
    #pragma unroll
    for (int nt = 0; nt < 8; ++nt) {
        int col = h*HD + nt*8 + 2*t;
        size_t i0 = (size_t)(b*S_LEN + sg0)*DMODEL + col;
        size_t i1 = (size_t)(b*S_LEN + sg0 + 8)*DMODEL + col;
        float f0 = o[nt][0]*inv0, f1 = o[nt][1]*inv0;
        float f2 = o[nt][2]*inv1, f3 = o[nt][3]*inv1;
        uint32_t hv0 = cvt_bf16x2(f1, f0);
        uint32_t lv0 = cvt_bf16x2(f1 - __uint_as_float(hv0 & 0xffff0000u),
                                  f0 - __uint_as_float(hv0 << 16));
        uint32_t hv1 = cvt_bf16x2(f3, f2);
        uint32_t lv1 = cvt_bf16x2(f3 - __uint_as_float(hv1 & 0xffff0000u),
                                  f2 - __uint_as_float(hv1 << 16));
        *(uint32_t*)(g_aHi + i0) = hv0;
        *(uint32_t*)(g_aLo + i0) = lv0;
        *(uint32_t*)(g_aHi + i1) = hv1;
        *(uint32_t*)(g_aLo + i1) = lv1;
    }
}

// ---------------------------------------------------------------------------
extern "C" void kernel_launch(void* const* d_in, const int* in_sizes, int n_in,
                              void* d_out, int out_size) {
    const float* hs   = (const float*)d_in[0];   // [2,2048,1024]
    const float* wqkv = (const float*)d_in[1];   // [1024,3072]
    const float* wout = (const float*)d_in[2];   // [1024,1024]
    const int*   pos  = (const int*)  d_in[3];   // pos_xyz (int32 or int64)
    float* out = (float*)d_out;

    const int n_pos = NTOK * 3;

    detect_pos64<<<1, 256>>>(pos, n_pos);
    convert_pos<<<(n_pos + 255)/256, 256>>>(pos, n_pos);
    build_tables<<<1, 1024>>>();

    // Weight transposes + bf16 splits
    transpose_split<<<dim3(3*DMODEL/32, DMODEL/32), dim3(32, 8)>>>(wqkv, DMODEL, 3*DMODEL, 0);
    transpose_split<<<dim3(DMODEL/32, DMODEL/32), dim3(32, 8)>>>(wout, DMODEL, DMODEL, 1);

    cudaFuncSetAttribute(mma_gemm, cudaFuncAttributeMaxDynamicSharedMemorySize, GEMM_SMEM);

    // QKV projection: double-buffered, in-kernel A split, RoPE-fused epilogue
    mma_gemm<<<dim3(3*DMODEL/128, NTOK/128), 256, GEMM_SMEM>>>(hs, nullptr, 3*DMODEL, 1);

    // Attention (tensor cores, double-buffered K/V)
    cudaFuncSetAttribute(attention_mma,
                         cudaFuncAttributeMaxDynamicSharedMemorySize, ATT_SMEM);
    attention_mma<<<dim3(S_LEN/128, NBH), 256, ATT_SMEM>>>();

    // Output projection: fully async A+B
    mma_gemm<<<dim3(DMODEL/128, NTOK/128), 256, GEMM_SMEM>>>(nullptr, out, DMODEL, 2);
}